// round 15
// baseline (speedup 1.0000x reference)
#include <cuda_runtime.h>
#include <cuda_bf16.h>
#include <stdint.h>

#define NN 96
#define DD 64
#define CC 30

// Scratch (__device__ globals; no allocation allowed)
__device__ float    g_mat[NN * NN];         // mat rows (written by prepA)
__device__ unsigned g_smask[NN * 3];
__device__ unsigned g_dmask[NN * 3];
__device__ float    g_rnum[NN], g_rq[NN];   // per-row eps partials
__device__ unsigned g_cmask[NN * NN * 4];   // 96-bit mask per (i,p), stride 4 words

// ---------------------------------------------------------------------------
// prepA: 96 blocks x 512. Block i owns anchor i. Kernel boundary = barrier.
//   stage logits+labels (smem, 18 iters) ->
//   CONCURRENT: warps 0..2 (tid<96): fused norm+dot sweep over sx
//               warp 3: row-i label masks via ballots
//   -> sync -> srow finalize (acc kept in register) -> eps partials (warp 0).
// All summation orders identical to the R14-passing kernel:
//   sc  = sum_d v_t^2            (d-ascending)  == old norm sum
//   acc = sum_d v_i * v_t        (d-ascending)  == old dot
//   srow = -acc * rn[i] * rn[t]                 == old formula
// ---------------------------------------------------------------------------
__global__ __launch_bounds__(512) void prepA(const float* __restrict__ logits,
                                             const float* __restrict__ labels) {
    __shared__ float    sx[NN * 65];     // logits, rows padded to 65
    __shared__ float    slab[NN * CC];   // labels
    __shared__ float    rn[NN];          // rsqrt norms
    __shared__ float    srow[NN];        // mat row i
    __shared__ unsigned sm[3], dm[3];    // smask/dmask row i

    const int tid  = threadIdx.x;
    const int ianc = blockIdx.x;         // anchor i
    const int warp = tid >> 5, lane = tid & 31;

    // ---- stage inputs (coalesced, 512-wide) ----
    #pragma unroll
    for (int it = 0; it < 12; it++) {                 // 6144 = 12*512
        int t = it * 512 + tid;
        sx[(t >> 6) * 65 + (t & 63)] = logits[t];
    }
    #pragma unroll
    for (int it = 0; it < 6; it++) {                  // 2880 = 96*30
        int t = it * 512 + tid;
        if (t < NN * CC) slab[t] = labels[t];
    }
    __syncthreads();

    // ---- CONCURRENT: fused norm+dot (warps 0..2) | labels (warp 3) ----
    float acc = 0.f;                                  // dot(row_i, row_tid)
    if (tid < NN) {
        float sc = 0.f;
        #pragma unroll
        for (int d = 0; d < DD; d++) {
            float vi = sx[ianc * 65 + d];             // broadcast LDS
            float vt = sx[tid  * 65 + d];
            sc  += vt * vt;                           // == old norm order
            acc += vi * vt;                           // == old dot order
        }
        rn[tid] = rsqrtf(sc);
    } else if (warp == 3) {
        #pragma unroll
        for (int wd = 0; wd < 3; wd++) {
            int j = wd * 32 + lane;
            float a = 0.f;
            #pragma unroll
            for (int cc = 0; cc < CC; cc++) a += slab[ianc * CC + cc] * slab[j * CC + cc];
            bool same_raw = a > 0.f;
            unsigned sb = __ballot_sync(0xffffffffu, same_raw && (j != ianc));
            unsigned db = __ballot_sync(0xffffffffu, !same_raw);
            if (lane == 0) {
                sm[wd] = sb;  dm[wd] = db;
                g_smask[ianc * 3 + wd] = sb;
                g_dmask[ianc * 3 + wd] = db;
            }
        }
    }
    __syncthreads();                                  // rn[], sm/dm ready

    // ---- srow finalize (same formula; acc held in register) ----
    if (tid < NN) {
        float v = -acc * rn[ianc] * rn[tid];
        srow[tid] = v;
        g_mat[ianc * NN + tid] = v;                   // persist for prepB
    }
    __syncthreads();

    // ---- row-i eps partials (warp 0; identical lane/word/shuffle pattern) ----
    if (warp == 0) {
        float S = 0.f, ds = 0.f, ms = 0.f, md = 0.f;
        #pragma unroll
        for (int jj = 0; jj < 3; jj++) {
            float mv = srow[jj * 32 + lane];
            if ((sm[jj] >> lane) & 1u) { S += 1.f; ms += mv; }
            if ((dm[jj] >> lane) & 1u) { ds += 1.f; md += mv; }
        }
        #pragma unroll
        for (int o = 16; o; o >>= 1) {
            S  += __shfl_xor_sync(0xffffffffu, S,  o);
            ds += __shfl_xor_sync(0xffffffffu, ds, o);
            ms += __shfl_xor_sync(0xffffffffu, ms, o);
            md += __shfl_xor_sync(0xffffffffu, md, o);
        }
        if (lane == 0) {
            g_rnum[ianc] = (S - 1.f) * (S * md - ms * ds);
            g_rq[ianc]   = 0.5f * S * (S - 1.f) * ds;
        }
    }
}

// ---------------------------------------------------------------------------
// prepB: 96 blocks x 256 (verbatim from the passing R14 kernel).
// Block i: redundant serial eps reduce (identical i-ascending order in every
// block -> deterministic, same value), then cmask ballots for anchor i.
// ---------------------------------------------------------------------------
__global__ __launch_bounds__(256) void prepB() {
    __shared__ float    srow[NN];
    __shared__ unsigned sm[3], dm[3];
    __shared__ float    s_eps;

    const int tid  = threadIdx.x;
    const int ianc = blockIdx.x;
    const int warp = tid >> 5, lane = tid & 31;

    if (tid < NN) srow[tid] = g_mat[ianc * NN + tid];
    if (tid >= NN && tid < NN + 3) {
        sm[tid - NN] = g_smask[ianc * 3 + (tid - NN)];
        dm[tid - NN] = g_dmask[ianc * 3 + (tid - NN)];
    }
    if (tid == 128) {   // serial reduce: identical order in every block
        float num = 0.f, q = 0.f;
        for (int i = 0; i < NN; i++) { num += g_rnum[i]; q += g_rq[i]; }
        float mean_delta = num / fmaxf(2.f * q, 1.f);
        s_eps = fmaxf(mean_delta * 0.5f, 0.f);   // relu(mean_delta / K_DELTA)
    }
    __syncthreads();
    const float eps = s_eps;

    // ---- cmask for anchor i (8 warps, same ballot math as before) ----
    for (int p = warp; p < NN; p += 8) {
        unsigned sp = (sm[p >> 5] >> (p & 31)) & 1u;
        float matp = srow[p];
        #pragma unroll
        for (int wd = 0; wd < 3; wd++) {
            float m = srow[wd * 32 + lane] - matp;
            bool cc = sp && (((dm[wd] >> lane) & 1u) != 0u) && (m > 0.f) && (m <= eps);
            unsigned b = __ballot_sync(0xffffffffu, cc);
            if (lane == 0) g_cmask[(ianc * NN + p) * 4 + wd] = b;
        }
    }
}

// ---------------------------------------------------------------------------
// writer: the proven 48us full-slab shape (verbatim). One block per (i,j);
// stage the 96x3 AND-ed words (zeroed for k<=j) in smem; 256 threads emit
// 9 coalesced float4 each via streaming stores.
// ---------------------------------------------------------------------------
__global__ __launch_bounds__(256) void writer(float4* __restrict__ out) {
    __shared__ unsigned sw[NN * 3];
    const int r2 = blockIdx.x;           // i*96 + j
    const int j  = r2 % NN;
    const int ibase = r2 - j;            // i*96
    const int tid = threadIdx.x;

    for (int t = tid; t < NN * 3; t += 256) {
        int k  = t / 3;
        int wd = t - k * 3;
        unsigned v = 0u;
        if (k > j)
            v = g_cmask[(r2 << 2) + wd] & g_cmask[((ibase + k) << 2) + wd];
        sw[t] = v;                       // layout sw[k*3 + wd]
    }
    __syncthreads();

    float4* o = out + (size_t)r2 * 2304; // 96*96/4 float4 per (i,j)
    const unsigned ONEF = 0x3f800000u;
    #pragma unroll
    for (int p = 0; p < 9; p++) {
        int pos = p * 256 + tid;         // 0..2303
        int k   = pos / 24;              // 24 float4 per n-row
        int n4  = pos - k * 24;
        unsigned w = sw[k * 3 + (n4 >> 3)];
        unsigned b = w >> ((n4 & 7) * 4);
        float4 v;
        v.x = __uint_as_float(ONEF & (0u - (b & 1u)));
        v.y = __uint_as_float(ONEF & (0u - ((b >> 1) & 1u)));
        v.z = __uint_as_float(ONEF & (0u - ((b >> 2) & 1u)));
        v.w = __uint_as_float(ONEF & (0u - ((b >> 3) & 1u)));
        __stcs(&o[pos], v);              // streaming store: evict-first
    }
}

// ---------------------------------------------------------------------------
extern "C" void kernel_launch(void* const* d_in, const int* in_sizes, int n_in,
                              void* d_out, int out_size) {
    const float* logits = (const float*)d_in[0];   // [96,64]
    const float* labels = (const float*)d_in[1];   // [96,30]

    prepA<<<NN, 512>>>(logits, labels);
    prepB<<<NN, 256>>>();
    writer<<<NN * NN, 256>>>((float4*)d_out);
}